// round 6
// baseline (speedup 1.0000x reference)
#include <cuda_runtime.h>
#include <cuda_fp16.h>

// ---------------------------------------------------------------------------
// SSIM3D: two fp32 volumes (4,1,160,160,160), 11-tap separable Gaussian,
// 5 statistics (mu1, mu2, E11, E22, E12), scalar mean output.
//
// R6: tiled 2-pass with taller tiles + packed f32x2 everywhere:
//  - pass_xy: 32(x) x 80(y) tiles (region 42x90), x-conv then y-conv,
//    (m1,m2)/(e11,e22) FFMA2 chains, fp16 mid. Dynamic smem 90.4 kB.
//  - pass_z: 32(x) x 80(z) tiles (region 90), z-conv FFMA2, SSIM map fully
//    packed f32x2 incl. Newton reciprocal. Dynamic smem 64.8 kB.
// ---------------------------------------------------------------------------

typedef unsigned long long u64t;

namespace {
constexpr int D    = 160;
constexpr int DD   = D * D;                 // 25600
constexpr int NB   = 4;
constexpr long long VOL  = (long long)D * DD;       // 4,096,000
constexpr long long NIMG = (long long)NB * VOL;     // 16,384,000
constexpr int RXA = 42;   // pass_xy region width  (x)
constexpr int RYA = 90;   // pass_xy region height (y)
constexpr int SXA = 43;   // u64 stride, interleaved input tile
constexpr int TSA = 33;   // stride of x-conv planes
constexpr int RZZ = 90;   // pass_z region (z)
constexpr int UZ  = 18;   // u64 stride, pass_z tile (x-pairs)
constexpr float C1 = 0.0001f;
constexpr float C2 = 0.0009f;
// pass_xy dynamic smem layout (u64 units)
constexpr int OFF_TM = RYA * SXA;            // 3870
constexpr int OFF_TE = OFF_TM + RYA * TSA;   // 6840
constexpr int OFF_TS = OFF_TE + RYA * TSA;   // 9810
constexpr int SMEM_XY = (OFF_TS + (RYA * TSA + 1) / 2) * 8;   // 90368 B
constexpr int SMEM_Z  = 5 * RZZ * UZ * 8;                     // 64800 B
}

__device__ constexpr float W[11] = {
    0.00102838f, 0.00759876f, 0.03600077f, 0.10936070f, 0.21300554f,
    0.26601173f,
    0.21300554f, 0.10936070f, 0.03600077f, 0.00759876f, 0.00102838f};

// 5 channels x 4 batches x 160^3 halfs = 163.84 MB scratch.
__device__ __half g_mid[5ll * 16384000ll];
__device__ double g_sum;

// ---- packed f32x2 helpers ----
__device__ __forceinline__ u64t pk(float x, float y) {
    u64t r; asm("mov.b64 %0, {%1, %2};" : "=l"(r) : "f"(x), "f"(y)); return r;
}
__device__ __forceinline__ float2 unpk(u64t v) {
    float2 f; asm("mov.b64 {%0, %1}, %2;" : "=f"(f.x), "=f"(f.y) : "l"(v));
    return f;
}
__device__ __forceinline__ u64t fma2(u64t a, u64t w, u64t d) {
    asm("fma.rn.f32x2 %0, %1, %2, %0;" : "+l"(d) : "l"(a), "l"(w));
    return d;
}
__device__ __forceinline__ u64t mul2(u64t a, u64t b) {
    u64t r; asm("mul.rn.f32x2 %0, %1, %2;" : "=l"(r) : "l"(a), "l"(b));
    return r;
}
__device__ __forceinline__ u64t add2(u64t a, u64t b) {
    u64t r; asm("add.rn.f32x2 %0, %1, %2;" : "=l"(r) : "l"(a), "l"(b));
    return r;
}
__device__ __forceinline__ u64t neg2(u64t a) {
    return a ^ 0x8000000080000000ull;
}
// Packed reciprocal: bit-trick seed (no cross-lane borrow: both halves of
// den are positive with bits < 0x7EF311C3) + 3 Newton steps. FMA-pipe only.
__device__ __forceinline__ u64t rcp2(u64t x, u64t two2) {
    u64t r = 0x7EF311C37EF311C3ull - x;
#pragma unroll
    for (int it = 0; it < 3; it++)
        r = mul2(r, add2(two2, neg2(mul2(x, r))));
    return r;
}

// ---------------------------------------------------------------------------
// Pass A: x-conv then y-conv for one 32(x) x 80(y) tile of one z-slice.
// grid = (10 tiles, 160 z, 4 b), block = 576 threads.
// ---------------------------------------------------------------------------
__global__ void __launch_bounds__(576, 1)
pass_xy(const float* __restrict__ img1, const float* __restrict__ img2) {
    extern __shared__ u64t dsm[];
    u64t* sAC = dsm;                 // (a,c) interleaved input, [90][43]
    u64t* tm  = dsm + OFF_TM;        // (m1,m2)   x-conv plane, [90][33]
    u64t* te  = dsm + OFF_TE;        // (e11,e22) x-conv plane, [90][33]
    float* ts = (float*)(dsm + OFF_TS);   // e12 x-conv plane, [90][33]

    const int tile = blockIdx.x;            // 0..9
    const int x0 = (tile % 5) * 32;
    const int y0 = (tile / 5) * 80;
    const int z  = blockIdx.y;
    const int b  = blockIdx.z;
    const int tid = threadIdx.x;

    if (tile == 0 && z == 0 && b == 0 && tid == 0) g_sum = 0.0;  // fold init

    const float* p1 = img1 + (long long)b * VOL + (long long)z * DD;
    const float* p2 = img2 + (long long)b * VOL + (long long)z * DD;

    // Stage 1: prefetch 42x90 halo region (MLP-batched), store interleaved.
    {
        float ra[7], rc[7];
#pragma unroll
        for (int it = 0; it < 7; it++) {
            const int l = tid + it * 576;
            float a = 0.f, c = 0.f;
            if (l < RYA * RXA) {
                const int j = l / RXA, i = l - j * RXA;
                const int gy = y0 - 5 + j;
                const int gx = x0 - 5 + i;
                if (gy >= 0 && gy < D && gx >= 0 && gx < D) {
                    a = p1[gy * D + gx];
                    c = p2[gy * D + gx];
                }
            }
            ra[it] = a; rc[it] = c;
        }
#pragma unroll
        for (int it = 0; it < 7; it++) {
            const int l = tid + it * 576;
            if (l < RYA * RXA)
                sAC[(l / RXA) * SXA + (l % RXA)] = pk(ra[it], rc[it]);
        }
    }
    __syncthreads();

    u64t W2[11];
#pragma unroll
    for (int k = 0; k < 11; k++) W2[k] = pk(W[k], W[k]);

    // Stage 2: x-conv, 90 rows x 8 chunks of 4 outputs = 720 units.
    for (int u = tid; u < RYA * 8; u += 576) {
        const int row   = u % RYA;
        const int chunk = u / RYA;
        const int base = row * SXA + chunk * 4;
        u64t ac[14], sq[14];
        float p12[14];
#pragma unroll
        for (int j = 0; j < 14; j++) ac[j] = sAC[base + j];
#pragma unroll
        for (int j = 0; j < 14; j++) {
            sq[j] = mul2(ac[j], ac[j]);
            const float2 t = unpk(ac[j]);
            p12[j] = t.x * t.y;
        }
#pragma unroll
        for (int i = 0; i < 4; i++) {
            u64t am = 0ull, ae = 0ull;
            float a12 = 0.f;
#pragma unroll
            for (int k = 0; k < 11; k++) {
                am  = fma2(ac[i + k], W2[k], am);
                ae  = fma2(sq[i + k], W2[k], ae);
                a12 = fmaf(W[k], p12[i + k], a12);
            }
            const int x = chunk * 4 + i;
            tm[row * TSA + x] = am;
            te[row * TSA + x] = ae;
            ts[row * TSA + x] = a12;
        }
    }
    __syncthreads();

    // Stage 3: y-conv (80 outputs in 8 chunks of 10), write fp16 planes.
    // 768 units: g=0 (m-pair), g=1 (e-pair), g=2 (e12 scalar).
    const long long cs = (long long)NB * VOL;
    for (int u = tid; u < 768; u += 576) {
        const int g = u >> 8;
        const int r = u & 255;
        const int tx = r & 31;
        const int sub = r >> 5;              // y chunk of 10
        __half* o0 = g_mid + (long long)b * VOL + (long long)z * DD + x0 + tx;

        if (g < 2) {
            const u64t* tp = (g == 0) ? tm : te;
            __half* q0 = o0 + (g == 0 ? 0 : 2 * cs);
            __half* q1 = q0 + cs;
            u64t v[20];
#pragma unroll
            for (int j = 0; j < 20; j++)
                v[j] = tp[(sub * 10 + j) * TSA + tx];
#pragma unroll
            for (int i = 0; i < 10; i++) {
                u64t acc = 0ull;
#pragma unroll
                for (int k = 0; k < 11; k++) acc = fma2(v[i + k], W2[k], acc);
                const float2 f = unpk(acc);
                const long long yo = (long long)(y0 + sub * 10 + i) * D;
                q0[yo] = __float2half_rn(f.x);
                q1[yo] = __float2half_rn(f.y);
            }
        } else {
            __half* q4 = o0 + 4 * cs;
            float v[20];
#pragma unroll
            for (int j = 0; j < 20; j++)
                v[j] = ts[(sub * 10 + j) * TSA + tx];
#pragma unroll
            for (int i = 0; i < 10; i++) {
                float acc = 0.f;
#pragma unroll
                for (int k = 0; k < 11; k++) acc = fmaf(W[k], v[i + k], acc);
                q4[(long long)(y0 + sub * 10 + i) * D] = __float2half_rn(acc);
            }
        }
    }
}

// ---------------------------------------------------------------------------
// Pass B: z-conv + packed SSIM + reduction for one 32(x) x 80(z) tile.
// grid = (10 tiles, 160 y, 4 b), block = 256 threads.
// ---------------------------------------------------------------------------
__global__ void __launch_bounds__(256, 2) pass_z() {
    extern __shared__ u64t u5[];     // [5][90][18] x-pairs, fp32
    __shared__ float red[8];

    const int tile = blockIdx.x;
    const int x0 = (tile % 5) * 32;
    const int z0 = (tile / 5) * 80;
    const int y  = blockIdx.y;
    const int b  = blockIdx.z;
    const int tid = threadIdx.x;

    const long long cs = (long long)NB * VOL;
    const __half* basep = g_mid + (long long)b * VOL + (long long)y * D + x0;

    // Fill: 5 ch x 90 z-rows x 8 half4-quads (uint2 loads, float4 stores).
    for (int l = tid; l < 5 * RZZ * 8; l += 256) {
        const int ch = l / (RZZ * 8);
        const int rem = l - ch * (RZZ * 8);
        const int zz = rem >> 3;
        const int q  = rem & 7;
        const int gz = z0 - 5 + zz;
        float4 f = make_float4(0.f, 0.f, 0.f, 0.f);
        if (gz >= 0 && gz < D) {
            const uint2 h = *(const uint2*)(basep + ch * cs +
                                            (long long)gz * DD + 4 * q);
            const float2 f0 = __half22float2(*(const __half2*)&h.x);
            const float2 f1 = __half22float2(*(const __half2*)&h.y);
            f = make_float4(f0.x, f0.y, f1.x, f1.y);
        }
        ((float4*)u5)[(ch * RZZ + zz) * (UZ / 2) + q] = f;
    }
    __syncthreads();

    u64t W2[11];
#pragma unroll
    for (int k = 0; k < 11; k++) W2[k] = pk(W[k], W[k]);

    // Each thread: one x-pair (16), 5 z-outputs (zc = 0..15).
    const int xp = tid & 15;
    const int zc = tid >> 4;
    u64t rr[5][5];
#pragma unroll
    for (int ch = 0; ch < 5; ch++) {
        u64t v[15];
#pragma unroll
        for (int j = 0; j < 15; j++)
            v[j] = u5[(ch * RZZ + zc * 5 + j) * UZ + xp];
#pragma unroll
        for (int i = 0; i < 5; i++) {
            u64t acc = 0ull;
#pragma unroll
            for (int k = 0; k < 11; k++) acc = fma2(v[i + k], W2[k], acc);
            rr[ch][i] = acc;
        }
    }

    // Packed SSIM map.
    const u64t two2 = pk(2.f, 2.f);
    const u64t c1p  = pk(C1, C1);
    const u64t c2p  = pk(C2, C2);
    u64t lacc = 0ull;
#pragma unroll
    for (int i = 0; i < 5; i++) {
        const u64t mu1 = rr[0][i], mu2 = rr[1][i];
        const u64t e11 = rr[2][i], e22 = rr[3][i], e12 = rr[4][i];
        const u64t mu1s = mul2(mu1, mu1);
        const u64t mu2s = mul2(mu2, mu2);
        const u64t mu12 = mul2(mu1, mu2);
        const u64t num1 = fma2(mu12, two2, c1p);
        const u64t num2 = fma2(add2(e12, neg2(mu12)), two2, c2p);
        const u64t den1 = add2(add2(mu1s, mu2s), c1p);
        const u64t den2 = add2(add2(add2(e11, neg2(mu1s)),
                                    add2(e22, neg2(mu2s))), c2p);
        const u64t num = mul2(num1, num2);
        const u64t den = mul2(den1, den2);
        lacc = fma2(num, rcp2(den, two2), lacc);
    }
    const float2 lf = unpk(lacc);
    float lsum = lf.x + lf.y;

    // Block reduction (8 warps).
#pragma unroll
    for (int o = 16; o > 0; o >>= 1)
        lsum += __shfl_xor_sync(0xffffffffu, lsum, o);
    if ((tid & 31) == 0) red[tid >> 5] = lsum;
    __syncthreads();
    if (tid == 0) {
        float s = 0.f;
#pragma unroll
        for (int w = 0; w < 8; w++) s += red[w];
        atomicAdd(&g_sum, (double)s);
    }
}

__global__ void fin_kernel(float* __restrict__ out) {
    out[0] = (float)(g_sum / (double)NIMG);
}

extern "C" void kernel_launch(void* const* d_in, const int* in_sizes, int n_in,
                              void* d_out, int out_size) {
    const float* img1 = (const float*)d_in[0];
    const float* img2 = (const float*)d_in[1];
    (void)in_sizes; (void)n_in; (void)out_size;

    cudaFuncSetAttribute(pass_xy, cudaFuncAttributeMaxDynamicSharedMemorySize,
                         SMEM_XY);
    cudaFuncSetAttribute(pass_z, cudaFuncAttributeMaxDynamicSharedMemorySize,
                         SMEM_Z);

    dim3 grid(10, 160, 4);
    pass_xy<<<grid, 576, SMEM_XY>>>(img1, img2);
    pass_z<<<grid, 256, SMEM_Z>>>();
    fin_kernel<<<1, 1>>>((float*)d_out);
}